// round 2
// baseline (speedup 1.0000x reference)
#include <cuda_runtime.h>
#include <cuda_bf16.h>
#include <cstdint>

#define BB 8
#define TT 1024
#define HH 128

// ---------------- static device scratch (no allocation APIs) ---------------
__device__ float g_Wx[BB * TT * 512];     // sLSTM input projections (+sb)
__device__ float g_h1[BB * TT * HH];      // sLSTM output sequence
__device__ float g_proj[BB * TT * 768];   // mLSTM projections [q k v i f o]
__device__ float g_htl[BB * TT * HH];     // o * h_tilde
__device__ float g_rden[BB * TT];         // 1 / denom

static __device__ __forceinline__ unsigned su32(const void* p) {
    return (unsigned)__cvta_generic_to_shared(p);
}

// ===========================================================================
// GEMM: Out[m][n] = (sum_k X[m][k]*Wseg[nloc][k] + Bseg[nloc]) * scale[seg]
//       optionally sigmoid.  mode 0: Out=g_Wx (N=512);  mode 1: Out=g_proj (N=768)
// ===========================================================================
struct GemmArgs {
    const float* W[6];
    const float* Bi[6];
    float scale[6];
    int sigm[6];
};

__global__ __launch_bounds__(256) void gemm_k(int mode, const float* __restrict__ Xp, GemmArgs a)
{
    const int K = 128;
    const int Ntot = (mode == 0) ? 512 : 768;
    const float* __restrict__ X = (mode == 0) ? Xp : g_h1;
    float* __restrict__ Out = (mode == 0) ? g_Wx : g_proj;

    __shared__ float Xs[64][68];  // [k_local][m_local]
    __shared__ float Ws[64][68];  // [k_local][n_local]

    const int bm = blockIdx.y * 64;
    const int bn = blockIdx.x * 64;
    const int seg = bn >> 7;          // 128-wide segments
    const int nl0 = bn & 127;         // segment-local n start
    const float* __restrict__ W = a.W[seg];
    const int tid = threadIdx.x;

    const int tx = tid & 15, ty = tid >> 4;
    float acc[4][4];
#pragma unroll
    for (int i = 0; i < 4; i++)
#pragma unroll
        for (int j = 0; j < 4; j++) acc[i][j] = 0.f;

    const int c4 = tid & 15;   // float4 column within 64-k chunk
    const int r0 = tid >> 4;   // 16 rows per pass

    for (int k0 = 0; k0 < K; k0 += 64) {
        __syncthreads();
#pragma unroll
        for (int rr = r0; rr < 64; rr += 16) {
            float4 xv = *(const float4*)&X[(size_t)(bm + rr) * K + k0 + c4 * 4];
            Xs[c4 * 4 + 0][rr] = xv.x; Xs[c4 * 4 + 1][rr] = xv.y;
            Xs[c4 * 4 + 2][rr] = xv.z; Xs[c4 * 4 + 3][rr] = xv.w;
            float4 wv = *(const float4*)&W[(size_t)(nl0 + rr) * K + k0 + c4 * 4];
            Ws[c4 * 4 + 0][rr] = wv.x; Ws[c4 * 4 + 1][rr] = wv.y;
            Ws[c4 * 4 + 2][rr] = wv.z; Ws[c4 * 4 + 3][rr] = wv.w;
        }
        __syncthreads();
#pragma unroll 4
        for (int k = 0; k < 64; k++) {
            float4 xm = *(const float4*)&Xs[k][ty * 4];
            float4 wn = *(const float4*)&Ws[k][tx * 4];
            float xa[4] = {xm.x, xm.y, xm.z, xm.w};
            float wa[4] = {wn.x, wn.y, wn.z, wn.w};
#pragma unroll
            for (int i = 0; i < 4; i++)
#pragma unroll
                for (int j = 0; j < 4; j++)
                    acc[i][j] = fmaf(xa[i], wa[j], acc[i][j]);
        }
    }

    const float sc = a.scale[seg];
    const int sg = a.sigm[seg];
    const float* __restrict__ Bp = a.Bi[seg];
#pragma unroll
    for (int i = 0; i < 4; i++) {
        int m = bm + ty * 4 + i;
#pragma unroll
        for (int j = 0; j < 4; j++) {
            int nl = nl0 + tx * 4 + j;
            float v = (acc[i][j] + Bp[nl]) * sc;
            if (sg) v = 1.f / (1.f + __expf(-v));
            Out[(size_t)m * Ntot + bn + tx * 4 + j] = v;
        }
    }
}

// ===========================================================================
// sLSTM scan: cluster of 2 CTAs per batch. Each CTA owns 64 units x 4 gates
// (256 rows), recurrent weights register-resident, h exchanged via DSMEM +
// cluster-scope mbarrier, double-buffered h.
// ===========================================================================
__global__ void __cluster_dims__(2, 1, 1) __launch_bounds__(256, 1)
slstm_k(const float* __restrict__ sR)
{
    __shared__ float h_s[2][HH];
    __shared__ float gs[256];
    __shared__ __align__(8) unsigned long long mbar;

    const int tid = threadIdx.x;
    const unsigned rank = (unsigned)(blockIdx.x & 1);
    const int batch = blockIdx.x >> 1;
    const int gate = tid >> 6;
    const int u = tid & 63;
    const int row = gate * 128 + (int)rank * 64 + u;

    // --- load recurrent weights into registers (one-time) ---
    float w[128];
    {
        const float4* wr = (const float4*)(sR + (size_t)row * 128);
#pragma unroll
        for (int k4 = 0; k4 < 32; k4++) {
            float4 v = wr[k4];
            w[4 * k4 + 0] = v.x; w[4 * k4 + 1] = v.y;
            w[4 * k4 + 2] = v.z; w[4 * k4 + 3] = v.w;
        }
    }
    if (tid < 128) { h_s[0][tid] = 0.f; h_s[1][tid] = 0.f; }
    if (tid == 0) {
        unsigned a = su32(&mbar);
        asm volatile("mbarrier.init.shared.b64 [%0], %1;" :: "r"(a), "r"(128) : "memory");
    }
    __syncthreads();
    asm volatile("barrier.cluster.arrive;\n\tbarrier.cluster.wait;\n" ::: "memory");

    float c = 0.f, n = 0.f, m = 0.f;
    const float* __restrict__ wx = g_Wx + (size_t)batch * TT * 512 + row;
    float* __restrict__ h1o = g_h1 + (size_t)batch * TT * HH;

    const unsigned mbar_l = su32(&mbar);
    unsigned mbar_r;
    asm("mapa.shared::cluster.u32 %0, %1, %2;" : "=r"(mbar_r) : "r"(mbar_l), "r"(rank ^ 1));

    float wx_cur = wx[0];

    for (int t = 0; t < TT; t++) {
        const int buf = t & 1;
        // prefetch next step's input projection
        float wx_nxt = (t + 1 < TT) ? wx[(size_t)(t + 1) * 512] : 0.f;

        // matvec: 4 split accumulators, h broadcast from smem
        float a0 = 0.f, a1 = 0.f, a2 = 0.f, a3 = 0.f;
        const float4* h4 = (const float4*)h_s[buf];
#pragma unroll
        for (int k4 = 0; k4 < 32; k4++) {
            float4 hv = h4[k4];
            a0 = fmaf(w[4 * k4 + 0], hv.x, a0);
            a1 = fmaf(w[4 * k4 + 1], hv.y, a1);
            a2 = fmaf(w[4 * k4 + 2], hv.z, a2);
            a3 = fmaf(w[4 * k4 + 3], hv.w, a3);
        }
        gs[tid] = ((a0 + a1) + (a2 + a3)) + wx_cur;
        __syncthreads();

        if (tid < 64) {
            float gi = gs[tid], gf = gs[64 + tid], gz = gs[128 + tid], go = gs[192 + tid];
            float mn = fmaxf(gf + m, gi);
            float ii = __expf(gi - mn);
            float ff = __expf(gf + m - mn);
            c = ff * c + ii * tanhf(gz);
            n = ff * n + ii;
            m = mn;
            float hn = (c / n) * (1.f / (1.f + __expf(-go)));

            const int gu = (int)rank * 64 + tid;
            const int nb = buf ^ 1;
            h_s[nb][gu] = hn;
            unsigned la = su32(&h_s[nb][gu]);
            unsigned ra;
            asm("mapa.shared::cluster.u32 %0, %1, %2;" : "=r"(ra) : "r"(la), "r"(rank ^ 1));
            asm volatile("st.shared::cluster.f32 [%0], %1;" :: "r"(ra), "f"(hn) : "memory");
            h1o[(size_t)t * HH + gu] = hn;

            asm volatile("mbarrier.arrive.release.cta.shared::cta.b64 _, [%0];"
                         :: "r"(mbar_l) : "memory");
            asm volatile("mbarrier.arrive.release.cluster.shared::cluster.b64 _, [%0];"
                         :: "r"(mbar_r) : "memory");
        }

        // wait for 64 local + 64 remote arrivals of this phase
        {
            unsigned par = (unsigned)(t & 1);
            asm volatile(
                "{\n\t"
                ".reg .pred P;\n\t"
                "WLOOP%=:\n\t"
                "mbarrier.try_wait.parity.acquire.cluster.shared::cta.b64 P, [%0], %1, 0x989680;\n\t"
                "@P bra.uni WDONE%=;\n\t"
                "bra.uni WLOOP%=;\n\t"
                "WDONE%=:\n\t"
                "}"
                :: "r"(mbar_l), "r"(par) : "memory");
        }
        wx_cur = wx_nxt;
    }

    asm volatile("barrier.cluster.arrive;\n\tbarrier.cluster.wait;\n" ::: "memory");
}

// ===========================================================================
// mLSTM: 128 row-CTAs (C-matrix rows in registers, no inter-CTA deps) +
//        8 denominator CTAs (n . q scan) in one kernel. Explicit prefetch.
// ===========================================================================
struct MVals {
    float it, ft, vv, oo;
    float4 k0, k1, q0, q1;
};

static __device__ __forceinline__ MVals ldvals(const float* __restrict__ P,
                                               int t, int R, int c0, bool lead)
{
    MVals v;
    const float* base = P + (size_t)t * 768;
    v.q0 = *(const float4*)(base + c0);
    v.q1 = *(const float4*)(base + c0 + 4);
    v.k0 = *(const float4*)(base + 128 + c0);
    v.k1 = *(const float4*)(base + 128 + c0 + 4);
    v.vv = __ldg(base + 256 + R);
    v.it = __ldg(base + 384 + R);
    v.ft = __ldg(base + 512 + R);
    v.oo = lead ? __ldg(base + 640 + R) : 0.f;
    return v;
}

__global__ __launch_bounds__(128) void mlstm_k()
{
    const int bi = blockIdx.x;
    const int tid = threadIdx.x;

    if (bi < 128) {
        // ---- C-row scan: batch b, rows [rg*8, rg*8+8) ----
        const int b = bi >> 4, rg = bi & 15;
        const int rl = tid >> 4, cg = tid & 15;
        const int R = rg * 8 + rl;
        const int c0 = cg * 8;
        const bool lead = (cg == 0);
        const float* __restrict__ P = g_proj + (size_t)b * TT * 768;
        float* __restrict__ HT = g_htl + (size_t)b * TT * HH;

        float C[8];
#pragma unroll
        for (int j = 0; j < 8; j++) C[j] = 0.f;
        float m = 0.f;

        MVals cur = ldvals(P, 0, R, c0, lead);
        for (int t = 0; t < TT; t++) {
            MVals nxt = (t + 1 < TT) ? ldvals(P, t + 1, R, c0, lead) : cur;

            float mn = fmaxf(cur.ft + m, cur.it);
            float ii = __expf(cur.it - mn);
            float ff = __expf(cur.ft + m - mn);
            m = mn;
            float iv = ii * cur.vv;

            float kq[8] = {cur.k0.x, cur.k0.y, cur.k0.z, cur.k0.w,
                           cur.k1.x, cur.k1.y, cur.k1.z, cur.k1.w};
            float qq[8] = {cur.q0.x, cur.q0.y, cur.q0.z, cur.q0.w,
                           cur.q1.x, cur.q1.y, cur.q1.z, cur.q1.w};
            float ht = 0.f;
#pragma unroll
            for (int j = 0; j < 8; j++) {
                C[j] = fmaf(ff, C[j], iv * kq[j]);
                ht = fmaf(C[j], qq[j], ht);
            }
            // reduce across the 16 threads owning this row (16-aligned lane groups)
#pragma unroll
            for (int s = 8; s >= 1; s >>= 1)
                ht += __shfl_xor_sync(0xffffffffu, ht, s);
            if (lead) HT[(size_t)t * HH + R] = cur.oo * ht;

            cur = nxt;
        }
    } else {
        // ---- denominator scan: batch bi-128, one warp, 4 units per lane ----
        if (tid >= 32) return;
        const int b = bi - 128;
        const int j0 = tid * 4;
        const float* __restrict__ P = g_proj + (size_t)b * TT * 768;
        float* __restrict__ RD = g_rden + (size_t)b * TT;

        float n4[4] = {0, 0, 0, 0};
        float m4[4] = {0, 0, 0, 0};

        const float* base0 = P;
        float4 qv = *(const float4*)(base0 + j0);
        float4 kv = *(const float4*)(base0 + 128 + j0);
        float4 iv = *(const float4*)(base0 + 384 + j0);
        float4 fv = *(const float4*)(base0 + 512 + j0);

        for (int t = 0; t < TT; t++) {
            float4 nq = qv, nk = kv, ni = iv, nf = fv;
            if (t + 1 < TT) {
                const float* bs = P + (size_t)(t + 1) * 768;
                nq = *(const float4*)(bs + j0);
                nk = *(const float4*)(bs + 128 + j0);
                ni = *(const float4*)(bs + 384 + j0);
                nf = *(const float4*)(bs + 512 + j0);
            }
            float qa[4] = {qv.x, qv.y, qv.z, qv.w};
            float ka[4] = {kv.x, kv.y, kv.z, kv.w};
            float ia[4] = {iv.x, iv.y, iv.z, iv.w};
            float fa[4] = {fv.x, fv.y, fv.z, fv.w};
            float dot = 0.f;
#pragma unroll
            for (int s = 0; s < 4; s++) {
                float mn = fmaxf(fa[s] + m4[s], ia[s]);
                float ii = __expf(ia[s] - mn);
                float ff = __expf(fa[s] + m4[s] - mn);
                m4[s] = mn;
                n4[s] = fmaf(ff, n4[s], ii * ka[s]);
                dot = fmaf(n4[s], qa[s], dot);
            }
#pragma unroll
            for (int s = 16; s >= 1; s >>= 1)
                dot += __shfl_xor_sync(0xffffffffu, dot, s);
            if (tid == 0) RD[t] = 1.f / fmaxf(fabsf(dot), 1.f);

            qv = nq; kv = nk; iv = ni; fv = nf;
        }
    }
}

// ===========================================================================
// Final combine: out = htl * rden (broadcast per row)
// ===========================================================================
__global__ __launch_bounds__(256) void comb_k(float* __restrict__ out)
{
    int i = blockIdx.x * 256 + threadIdx.x;         // float4 index
    float4 v = ((const float4*)g_htl)[i];
    float r = g_rden[i >> 5];                       // 32 float4 per 128-row
    v.x *= r; v.y *= r; v.z *= r; v.w *= r;
    ((float4*)out)[i] = v;
}

// ===========================================================================
extern "C" void kernel_launch(void* const* d_in, const int* in_sizes, int n_in,
                              void* d_out, int out_size)
{
    const float* x  = (const float*)d_in[0];
    const float* sW = (const float*)d_in[1];
    const float* sR = (const float*)d_in[2];
    const float* sb = (const float*)d_in[3];
    const float* Wq = (const float*)d_in[4];
    const float* Wk = (const float*)d_in[5];
    const float* Wv = (const float*)d_in[6];
    const float* Wi = (const float*)d_in[7];
    const float* Wf = (const float*)d_in[8];
    const float* Wo = (const float*)d_in[9];
    const float* bq = (const float*)d_in[10];
    const float* bk = (const float*)d_in[11];
    const float* bv = (const float*)d_in[12];
    const float* bi = (const float*)d_in[13];
    const float* bf = (const float*)d_in[14];
    const float* bo = (const float*)d_in[15];

    // GEMM1: Wx = x @ sW^T + sb  (segments = 4 x 128 rows of sW)
    GemmArgs a1;
    for (int s = 0; s < 6; s++) {
        int ss = (s < 4) ? s : 3;
        a1.W[s] = sW + (size_t)ss * 128 * 128;
        a1.Bi[s] = sb + (size_t)ss * 128;
        a1.scale[s] = 1.f;
        a1.sigm[s] = 0;
    }
    gemm_k<<<dim3(8, 128), 256>>>(0, x, a1);

    // sLSTM scan (cluster 2 per batch)
    slstm_k<<<16, 256>>>(sR);

    // GEMM2: proj = h1 @ [Wq Wk Wv Wi Wf Wo]^T + biases; k scaled, o sigmoided
    GemmArgs a2;
    const float* Ws2[6] = {Wq, Wk, Wv, Wi, Wf, Wo};
    const float* Bs2[6] = {bq, bk, bv, bi, bf, bo};
    const float inv_sqrt_h = 0.08838834764831845f;  // 1/sqrt(128)
    for (int s = 0; s < 6; s++) {
        a2.W[s] = Ws2[s];
        a2.Bi[s] = Bs2[s];
        a2.scale[s] = (s == 1) ? inv_sqrt_h : 1.f;
        a2.sigm[s] = (s == 5) ? 1 : 0;
    }
    gemm_k<<<dim3(12, 128), 256>>>(1, nullptr, a2);

    // mLSTM row scans + denominator scans
    mlstm_k<<<136, 128>>>();

    // Final combine
    comb_k<<<1024, 256>>>((float*)d_out);
}

// round 3
// speedup vs baseline: 1.2762x; 1.2762x over previous
#include <cuda_runtime.h>
#include <cuda_bf16.h>
#include <cstdint>

#define BB 8
#define TT 1024
#define HH 128
#define LL 64      // mLSTM chunk length
#define NC 16      // TT / LL

// ---------------- static device scratch (no allocation APIs) ---------------
__device__ float g_Wx[BB * TT * 512];     // sLSTM input projections (+sb)
__device__ float g_h1[BB * TT * HH];      // sLSTM output sequence
__device__ float g_proj[BB * TT * 768];   // mLSTM projections [q k v i f o]
__device__ float g_PM[BB * TT * HH];      // prefix-max of u within chunk
__device__ float g_Vt[BB * TT * HH];      // v * e^u
__device__ float g_P[BB * TT * HH];       // prefix-sum of k * e^u
__device__ float g_G[BB * TT * HH];       // intra-chunk numerator (pre e^{-M})
__device__ float g_Gc[BB * NC * HH * HH]; // per-chunk  Vt^T K
__device__ float g_Cst[BB * NC * HH * HH];// C state at each chunk start
__device__ float g_aL[BB * NC * HH];      // chunk-final cumsum(f)
__device__ float g_m0s[BB * NC * HH];     // m at chunk start
__device__ float g_n0s[BB * NC * HH];     // n at chunk start
__device__ float g_rden[BB * TT];         // 1 / denom

static __device__ __forceinline__ unsigned su32(const void* p) {
    return (unsigned)__cvta_generic_to_shared(p);
}

extern __shared__ float dsm[];

// ===========================================================================
// GEMM: Out[m][n] = (sum_k X[m][k]*Wseg[nloc][k] + Bseg[nloc]) * scale[seg]
//       optionally sigmoid.  mode 0: Out=g_Wx (N=512);  mode 1: Out=g_proj (N=768)
// ===========================================================================
struct GemmArgs {
    const float* W[6];
    const float* Bi[6];
    float scale[6];
    int sigm[6];
};

__global__ __launch_bounds__(256) void gemm_k(int mode, const float* __restrict__ Xp, GemmArgs a)
{
    const int K = 128;
    const int Ntot = (mode == 0) ? 512 : 768;
    const float* __restrict__ X = (mode == 0) ? Xp : g_h1;
    float* __restrict__ Out = (mode == 0) ? g_Wx : g_proj;

    __shared__ float Xs[64][68];
    __shared__ float Ws[64][68];

    const int bm = blockIdx.y * 64;
    const int bn = blockIdx.x * 64;
    const int seg = bn >> 7;
    const int nl0 = bn & 127;
    const float* __restrict__ W = a.W[seg];
    const int tid = threadIdx.x;

    const int tx = tid & 15, ty = tid >> 4;
    float acc[4][4];
#pragma unroll
    for (int i = 0; i < 4; i++)
#pragma unroll
        for (int j = 0; j < 4; j++) acc[i][j] = 0.f;

    const int c4 = tid & 15;
    const int r0 = tid >> 4;

    for (int k0 = 0; k0 < K; k0 += 64) {
        __syncthreads();
#pragma unroll
        for (int rr = r0; rr < 64; rr += 16) {
            float4 xv = *(const float4*)&X[(size_t)(bm + rr) * K + k0 + c4 * 4];
            Xs[c4 * 4 + 0][rr] = xv.x; Xs[c4 * 4 + 1][rr] = xv.y;
            Xs[c4 * 4 + 2][rr] = xv.z; Xs[c4 * 4 + 3][rr] = xv.w;
            float4 wv = *(const float4*)&W[(size_t)(nl0 + rr) * K + k0 + c4 * 4];
            Ws[c4 * 4 + 0][rr] = wv.x; Ws[c4 * 4 + 1][rr] = wv.y;
            Ws[c4 * 4 + 2][rr] = wv.z; Ws[c4 * 4 + 3][rr] = wv.w;
        }
        __syncthreads();
#pragma unroll 4
        for (int k = 0; k < 64; k++) {
            float4 xm = *(const float4*)&Xs[k][ty * 4];
            float4 wn = *(const float4*)&Ws[k][tx * 4];
            float xa[4] = {xm.x, xm.y, xm.z, xm.w};
            float wa[4] = {wn.x, wn.y, wn.z, wn.w};
#pragma unroll
            for (int i = 0; i < 4; i++)
#pragma unroll
                for (int j = 0; j < 4; j++)
                    acc[i][j] = fmaf(xa[i], wa[j], acc[i][j]);
        }
    }

    const float sc = a.scale[seg];
    const int sg = a.sigm[seg];
    const float* __restrict__ Bp = a.Bi[seg];
#pragma unroll
    for (int i = 0; i < 4; i++) {
        int m = bm + ty * 4 + i;
#pragma unroll
        for (int j = 0; j < 4; j++) {
            int nl = nl0 + tx * 4 + j;
            float v = (acc[i][j] + Bp[nl]) * sc;
            if (sg) v = 1.f / (1.f + __expf(-v));
            Out[(size_t)m * Ntot + bn + tx * 4 + j] = v;
        }
    }
}

// ===========================================================================
// sLSTM scan: cluster of 2 CTAs per batch (unchanged, known good)
// ===========================================================================
__global__ void __cluster_dims__(2, 1, 1) __launch_bounds__(256, 1)
slstm_k(const float* __restrict__ sR)
{
    __shared__ float h_s[2][HH];
    __shared__ float gs[256];
    __shared__ __align__(8) unsigned long long mbar;

    const int tid = threadIdx.x;
    const unsigned rank = (unsigned)(blockIdx.x & 1);
    const int batch = blockIdx.x >> 1;
    const int gate = tid >> 6;
    const int u = tid & 63;
    const int row = gate * 128 + (int)rank * 64 + u;

    float w[128];
    {
        const float4* wr = (const float4*)(sR + (size_t)row * 128);
#pragma unroll
        for (int k4 = 0; k4 < 32; k4++) {
            float4 v = wr[k4];
            w[4 * k4 + 0] = v.x; w[4 * k4 + 1] = v.y;
            w[4 * k4 + 2] = v.z; w[4 * k4 + 3] = v.w;
        }
    }
    if (tid < 128) { h_s[0][tid] = 0.f; h_s[1][tid] = 0.f; }
    if (tid == 0) {
        unsigned a = su32(&mbar);
        asm volatile("mbarrier.init.shared.b64 [%0], %1;" :: "r"(a), "r"(128) : "memory");
    }
    __syncthreads();
    asm volatile("barrier.cluster.arrive;\n\tbarrier.cluster.wait;\n" ::: "memory");

    float c = 0.f, n = 0.f, m = 0.f;
    const float* __restrict__ wx = g_Wx + (size_t)batch * TT * 512 + row;
    float* __restrict__ h1o = g_h1 + (size_t)batch * TT * HH;

    const unsigned mbar_l = su32(&mbar);
    unsigned mbar_r;
    asm("mapa.shared::cluster.u32 %0, %1, %2;" : "=r"(mbar_r) : "r"(mbar_l), "r"(rank ^ 1));

    float wx_cur = wx[0];

    for (int t = 0; t < TT; t++) {
        const int buf = t & 1;
        float wx_nxt = (t + 1 < TT) ? wx[(size_t)(t + 1) * 512] : 0.f;

        float a0 = 0.f, a1 = 0.f, a2 = 0.f, a3 = 0.f;
        const float4* h4 = (const float4*)h_s[buf];
#pragma unroll
        for (int k4 = 0; k4 < 32; k4++) {
            float4 hv = h4[k4];
            a0 = fmaf(w[4 * k4 + 0], hv.x, a0);
            a1 = fmaf(w[4 * k4 + 1], hv.y, a1);
            a2 = fmaf(w[4 * k4 + 2], hv.z, a2);
            a3 = fmaf(w[4 * k4 + 3], hv.w, a3);
        }
        gs[tid] = ((a0 + a1) + (a2 + a3)) + wx_cur;
        __syncthreads();

        if (tid < 64) {
            float gi = gs[tid], gf = gs[64 + tid], gz = gs[128 + tid], go = gs[192 + tid];
            float mn = fmaxf(gf + m, gi);
            float ii = __expf(gi - mn);
            float ff = __expf(gf + m - mn);
            c = ff * c + ii * tanhf(gz);
            n = ff * n + ii;
            m = mn;
            float hn = (c / n) * (1.f / (1.f + __expf(-go)));

            const int gu = (int)rank * 64 + tid;
            const int nb = buf ^ 1;
            h_s[nb][gu] = hn;
            unsigned la = su32(&h_s[nb][gu]);
            unsigned ra;
            asm("mapa.shared::cluster.u32 %0, %1, %2;" : "=r"(ra) : "r"(la), "r"(rank ^ 1));
            asm volatile("st.shared::cluster.f32 [%0], %1;" :: "r"(ra), "f"(hn) : "memory");
            h1o[(size_t)t * HH + gu] = hn;

            asm volatile("mbarrier.arrive.release.cta.shared::cta.b64 _, [%0];"
                         :: "r"(mbar_l) : "memory");
            asm volatile("mbarrier.arrive.release.cluster.shared::cluster.b64 _, [%0];"
                         :: "r"(mbar_r) : "memory");
        }

        {
            unsigned par = (unsigned)(t & 1);
            asm volatile(
                "{\n\t"
                ".reg .pred P;\n\t"
                "WLOOP%=:\n\t"
                "mbarrier.try_wait.parity.acquire.cluster.shared::cta.b64 P, [%0], %1, 0x989680;\n\t"
                "@P bra.uni WDONE%=;\n\t"
                "bra.uni WLOOP%=;\n\t"
                "WDONE%=:\n\t"
                "}"
                :: "r"(mbar_l), "r"(par) : "memory");
        }
        wx_cur = wx_nxt;
    }

    asm volatile("barrier.cluster.arrive;\n\tbarrier.cluster.wait;\n" ::: "memory");
}

// ===========================================================================
// mLSTM chunkwise-parallel pipeline
// ===========================================================================

// ---- prep: per (b,c,j): a=cumsum(f), u=i-a, PM=prefmax(u), Vt=v*e^u, P=cumsum(k*e^u)
__global__ __launch_bounds__(128) void prep_k()
{
    const int b = blockIdx.x >> 4;
    const int c = blockIdx.x & 15;
    const int j = threadIdx.x;
    const float* __restrict__ base = g_proj + ((size_t)(b * TT + c * LL) * 768);
    float a = 0.f, pm = -1e30f, p = 0.f;
    size_t oidx = (size_t)(b * TT + c * LL) * HH + j;
    for (int t = 0; t < LL; t++) {
        const float* row = base + (size_t)t * 768;
        float fv = row[512 + j];
        float iv = row[384 + j];
        float vv = row[256 + j];
        float kv = row[128 + j];
        a += fv;
        float u = iv - a;
        pm = fmaxf(pm, u);
        float eu = __expf(u);
        g_PM[oidx] = pm;
        g_Vt[oidx] = vv * eu;
        p = fmaf(kv, eu, p);
        g_P[oidx] = p;
        oidx += HH;
    }
    g_aL[(b * NC + c) * HH + j] = a;
}

// ---- chunk-boundary scan for m0 and n0 (per (b,j), 16 serial chunks)
__global__ __launch_bounds__(128) void n0m0_k()
{
    const int b = blockIdx.x;
    const int j = threadIdx.x;
    float m0 = 0.f, n0 = 0.f;
    for (int c = 0; c < NC; c++) {
        int ci = (b * NC + c) * HH + j;
        g_m0s[ci] = m0;
        g_n0s[ci] = n0;
        size_t li = (size_t)(b * TT + c * LL + (LL - 1)) * HH + j;
        float pml = g_PM[li];
        float pl  = g_P[li];
        float ML = fmaxf(m0, pml);
        n0 = __expf(m0 - ML) * n0 + __expf(-ML) * pl;
        m0 = g_aL[ci] + ML;
    }
}

// ---- Gc[b][c] = Vt^T K   (H x H per chunk)
__global__ __launch_bounds__(256) void gc_k()
{
    float* Vs = dsm;                // [64][128]
    float* Ks = dsm + 64 * 128;     // [64][132] padded
    const int b = blockIdx.x >> 4, c = blockIdx.x & 15;
    const int tid = threadIdx.x;
    const float* __restrict__ vb = g_Vt + (size_t)(b * TT + c * LL) * HH;
    const float* __restrict__ pb = g_proj + (size_t)(b * TT + c * LL) * 768;
    for (int i = tid; i < 2048; i += 256) {
        int s = i >> 5, j4 = i & 31;
        ((float4*)Vs)[i] = ((const float4*)vb)[i];
        float4 kv = *(const float4*)(pb + (size_t)s * 768 + 128 + j4 * 4);
        *(float4*)(Ks + s * 132 + j4 * 4) = kv;
    }
    __syncthreads();
    const int r0 = (tid >> 4) * 8, j0 = (tid & 15) * 8;
    float acc[8][8];
#pragma unroll
    for (int i = 0; i < 8; i++)
#pragma unroll
        for (int jj = 0; jj < 8; jj++) acc[i][jj] = 0.f;
    for (int s = 0; s < 64; s++) {
        float4 va = *(float4*)(Vs + s * 128 + r0);
        float4 vb4 = *(float4*)(Vs + s * 128 + r0 + 4);
        float4 ka = *(float4*)(Ks + s * 132 + j0);
        float4 kb = *(float4*)(Ks + s * 132 + j0 + 4);
        float vr[8] = {va.x, va.y, va.z, va.w, vb4.x, vb4.y, vb4.z, vb4.w};
        float kj[8] = {ka.x, ka.y, ka.z, ka.w, kb.x, kb.y, kb.z, kb.w};
#pragma unroll
        for (int i = 0; i < 8; i++)
#pragma unroll
            for (int jj = 0; jj < 8; jj++)
                acc[i][jj] = fmaf(vr[i], kj[jj], acc[i][jj]);
    }
    float* gout = g_Gc + (size_t)(b * NC + c) * (HH * HH);
#pragma unroll
    for (int i = 0; i < 8; i++)
#pragma unroll
        for (int jj = 0; jj < 8; jj += 4) {
            float4 v = {acc[i][jj], acc[i][jj + 1], acc[i][jj + 2], acc[i][jj + 3]};
            *(float4*)(gout + (size_t)(r0 + i) * HH + j0 + jj) = v;
        }
}

// ---- S = QK^T (causal-masked), G = S * Vt   per (b,c)
__global__ __launch_bounds__(256) void sg_k()
{
    float* Qs = dsm;                          // [64][128]
    float* KV = dsm + 64 * 128;               // [64][132] K then Vt
    float* Ss = dsm + 64 * 128 + 64 * 132;    // [64][65]
    const int b = blockIdx.x >> 4, c = blockIdx.x & 15;
    const int tid = threadIdx.x;
    const float* __restrict__ pb = g_proj + (size_t)(b * TT + c * LL) * 768;
    const float* __restrict__ vb = g_Vt + (size_t)(b * TT + c * LL) * HH;
    for (int i = tid; i < 2048; i += 256) {
        int s = i >> 5, j4 = i & 31;
        *(float4*)(Qs + s * 128 + j4 * 4) = *(const float4*)(pb + (size_t)s * 768 + j4 * 4);
        *(float4*)(KV + s * 132 + j4 * 4) = *(const float4*)(pb + (size_t)s * 768 + 128 + j4 * 4);
    }
    __syncthreads();
    // stage 1: S[t][s] = q_t . k_s, masked s<=t
    {
        const int t0 = (tid >> 4) * 4, s0 = (tid & 15) * 4;
        float acc[4][4];
#pragma unroll
        for (int i = 0; i < 4; i++)
#pragma unroll
            for (int s = 0; s < 4; s++) acc[i][s] = 0.f;
        for (int jj = 0; jj < 128; jj += 4) {
            float4 q[4], k[4];
#pragma unroll
            for (int i = 0; i < 4; i++) q[i] = *(float4*)(Qs + (t0 + i) * 128 + jj);
#pragma unroll
            for (int s = 0; s < 4; s++) k[s] = *(float4*)(KV + (s0 + s) * 132 + jj);
#pragma unroll
            for (int i = 0; i < 4; i++)
#pragma unroll
                for (int s = 0; s < 4; s++)
                    acc[i][s] += q[i].x * k[s].x + q[i].y * k[s].y
                               + q[i].z * k[s].z + q[i].w * k[s].w;
        }
#pragma unroll
        for (int i = 0; i < 4; i++)
#pragma unroll
            for (int s = 0; s < 4; s++)
                Ss[(t0 + i) * 65 + s0 + s] = (s0 + s <= t0 + i) ? acc[i][s] : 0.f;
    }
    __syncthreads();
    // swap K -> Vt in shared
    for (int i = tid; i < 2048; i += 256) {
        int s = i >> 5, j4 = i & 31;
        *(float4*)(KV + s * 132 + j4 * 4) = *(const float4*)(vb + (size_t)s * HH + j4 * 4);
    }
    __syncthreads();
    // stage 2: G[t][r] = sum_s Ss[t][s] * Vt[s][r]
    {
        const int t0 = (tid >> 5) * 8, r0 = (tid & 31) * 4;
        float acc[8][4];
#pragma unroll
        for (int i = 0; i < 8; i++)
#pragma unroll
            for (int jj = 0; jj < 4; jj++) acc[i][jj] = 0.f;
        for (int s = 0; s < 64; s++) {
            float4 v = *(float4*)(KV + s * 132 + r0);
#pragma unroll
            for (int i = 0; i < 8; i++) {
                float sv = Ss[(t0 + i) * 65 + s];
                acc[i][0] = fmaf(sv, v.x, acc[i][0]);
                acc[i][1] = fmaf(sv, v.y, acc[i][1]);
                acc[i][2] = fmaf(sv, v.z, acc[i][2]);
                acc[i][3] = fmaf(sv, v.w, acc[i][3]);
            }
        }
        float* gout = g_G + (size_t)(b * TT + c * LL) * HH;
#pragma unroll
        for (int i = 0; i < 8; i++) {
            float4 o4 = {acc[i][0], acc[i][1], acc[i][2], acc[i][3]};
            *(float4*)(gout + (size_t)(t0 + i) * HH + r0) = o4;
        }
    }
}

// ---- element-parallel C scan over 16 chunks: stores chunk-start C
__global__ __launch_bounds__(256) void cscan_k()
{
    int idx = blockIdx.x * 256 + threadIdx.x;
    int b = idx >> 14;
    int rj = idx & 16383;
    int r = rj >> 7;
    float C = 0.f;
    for (int c = 0; c < NC; c++) {
        size_t so = (size_t)(b * NC + c) * 16384 + rj;
        g_Cst[so] = C;
        float m0 = g_m0s[(b * NC + c) * HH + r];
        float pml = g_PM[(size_t)(b * TT + c * LL + LL - 1) * HH + r];
        float ML = fmaxf(m0, pml);
        C = __expf(m0 - ML) * C + __expf(-ML) * g_Gc[so];
    }
}

// ---- denominators (fully parallel over t): den = q . n_t
__global__ __launch_bounds__(256) void den_k()
{
    int g = blockIdx.x * 8 + (threadIdx.x >> 5);
    int lane = threadIdx.x & 31;
    int b = g >> 10, t = g & 1023;
    int c = t >> 6;
    int j0 = lane * 4;
    const float* q = g_proj + (size_t)(b * TT + t) * 768;
    size_t gi = (size_t)(b * TT + t) * HH;
    int ci = (b * NC + c) * HH;
    float d = 0.f;
#pragma unroll
    for (int s = 0; s < 4; s++) {
        int j = j0 + s;
        float m0 = g_m0s[ci + j];
        float pm = g_PM[gi + j];
        float g1 = __expf(fminf(0.f, m0 - pm));          // e^{m0 - M}
        float g2 = fminf(__expf(-m0), __expf(-pm));      // e^{-M}
        float nv = g1 * g_n0s[ci + j] + g2 * g_P[gi + j];
        d = fmaf(q[j], nv, d);
    }
#pragma unroll
    for (int s2 = 16; s2 >= 1; s2 >>= 1)
        d += __shfl_xor_sync(0xffffffffu, d, s2);
    if (lane == 0) g_rden[g] = 1.f / fmaxf(fabsf(d), 1.f);
}

// ---- final: h = o * (e^{m0-M} C0 q + e^{-M} G) * rden   (fully parallel)
__global__ __launch_bounds__(256) void inter_k(float* __restrict__ out)
{
    __shared__ float qs[16][128];
    const int blk = blockIdx.x;
    const int b = blk >> 6;
    const int c = (blk >> 2) & 15;
    const int tb = blk & 3;
    const int tid = threadIdx.x;
    const int r = tid >> 1, half = tid & 1;
    const int t0 = c * LL + tb * 16;

    const float* pb = g_proj + (size_t)(b * TT + t0) * 768;
    for (int i = tid; i < 512; i += 256) {
        int tt = i >> 5, j4 = i & 31;
        *(float4*)(&qs[tt][j4 * 4]) = *(const float4*)(pb + (size_t)tt * 768 + j4 * 4);
    }
    float Creg[64];
    const float* cb = g_Cst + (size_t)(b * NC + c) * 16384 + (size_t)r * 128 + half * 64;
#pragma unroll
    for (int i = 0; i < 16; i++) {
        float4 v = *(const float4*)(cb + i * 4);
        Creg[4 * i] = v.x; Creg[4 * i + 1] = v.y;
        Creg[4 * i + 2] = v.z; Creg[4 * i + 3] = v.w;
    }
    float m0 = g_m0s[(b * NC + c) * HH + r];
    float em0a = __expf(-m0);
    __syncthreads();

    for (int tt = 0; tt < 16; tt++) {
        float acc = 0.f;
        const float* qrow = &qs[tt][half * 64];
#pragma unroll
        for (int i = 0; i < 16; i++) {
            float4 qv = *(const float4*)(qrow + i * 4);
            acc = fmaf(Creg[4 * i], qv.x, acc);
            acc = fmaf(Creg[4 * i + 1], qv.y, acc);
            acc = fmaf(Creg[4 * i + 2], qv.z, acc);
            acc = fmaf(Creg[4 * i + 3], qv.w, acc);
        }
        acc += __shfl_xor_sync(0xffffffffu, acc, 1);
        if (half == 0) {
            int t = t0 + tt;
            size_t gi = (size_t)(b * TT + t) * HH + r;
            float pm = g_PM[gi];
            float g1 = __expf(fminf(0.f, m0 - pm));
            float g2 = fminf(em0a, __expf(-pm));
            float htl = g1 * acc + g2 * g_G[gi];
            float o = g_proj[(size_t)(b * TT + t) * 768 + 640 + r];
            out[gi] = o * htl * g_rden[b * TT + t];
        }
    }
}

// ===========================================================================
extern "C" void kernel_launch(void* const* d_in, const int* in_sizes, int n_in,
                              void* d_out, int out_size)
{
    const float* x  = (const float*)d_in[0];
    const float* sW = (const float*)d_in[1];
    const float* sR = (const float*)d_in[2];
    const float* sb = (const float*)d_in[3];
    const float* Wq = (const float*)d_in[4];
    const float* Wk = (const float*)d_in[5];
    const float* Wv = (const float*)d_in[6];
    const float* Wi = (const float*)d_in[7];
    const float* Wf = (const float*)d_in[8];
    const float* Wo = (const float*)d_in[9];
    const float* bq = (const float*)d_in[10];
    const float* bk = (const float*)d_in[11];
    const float* bv = (const float*)d_in[12];
    const float* bi = (const float*)d_in[13];
    const float* bf = (const float*)d_in[14];
    const float* bo = (const float*)d_in[15];

    const int GC_SMEM = (64 * 128 + 64 * 132) * 4;
    const int SG_SMEM = (64 * 128 + 64 * 132 + 64 * 65) * 4;
    cudaFuncSetAttribute(gc_k, cudaFuncAttributeMaxDynamicSharedMemorySize, GC_SMEM);
    cudaFuncSetAttribute(sg_k, cudaFuncAttributeMaxDynamicSharedMemorySize, SG_SMEM);

    // GEMM1: Wx = x @ sW^T + sb
    GemmArgs a1;
    for (int s = 0; s < 6; s++) {
        int ss = (s < 4) ? s : 3;
        a1.W[s] = sW + (size_t)ss * 128 * 128;
        a1.Bi[s] = sb + (size_t)ss * 128;
        a1.scale[s] = 1.f;
        a1.sigm[s] = 0;
    }
    gemm_k<<<dim3(8, 128), 256>>>(0, x, a1);

    // sLSTM scan
    slstm_k<<<16, 256>>>(sR);

    // GEMM2: proj = h1 @ [Wq Wk Wv Wi Wf Wo]^T + biases (k scaled, o sigmoided)
    GemmArgs a2;
    const float* Ws2[6] = {Wq, Wk, Wv, Wi, Wf, Wo};
    const float* Bs2[6] = {bq, bk, bv, bi, bf, bo};
    const float inv_sqrt_h = 0.08838834764831845f;
    for (int s = 0; s < 6; s++) {
        a2.W[s] = Ws2[s];
        a2.Bi[s] = Bs2[s];
        a2.scale[s] = (s == 1) ? inv_sqrt_h : 1.f;
        a2.sigm[s] = (s == 5) ? 1 : 0;
    }
    gemm_k<<<dim3(12, 128), 256>>>(1, nullptr, a2);

    // mLSTM chunkwise pipeline
    prep_k<<<BB * NC, 128>>>();
    gc_k<<<BB * NC, 256, GC_SMEM>>>();
    sg_k<<<BB * NC, 256, SG_SMEM>>>();
    n0m0_k<<<BB, 128>>>();
    cscan_k<<<(BB * HH * HH) / 256, 256>>>();
    den_k<<<(BB * TT) / 8, 256>>>();
    inter_k<<<BB * NC * 4, 256>>>((float*)d_out);
}

// round 4
// speedup vs baseline: 1.4004x; 1.0973x over previous
#include <cuda_runtime.h>
#include <cuda_bf16.h>
#include <cstdint>

#define BB 8
#define TT 1024
#define HH 128
#define LL 64      // mLSTM chunk length
#define NC 16      // TT / LL

// ---------------- static device scratch (no allocation APIs) ---------------
__device__ float g_Wx[BB * TT * 512];     // sLSTM input projections (+sb)
__device__ float g_h1[BB * TT * HH];      // sLSTM output sequence
__device__ float g_proj[BB * TT * 768];   // mLSTM projections [q k v i f o]
__device__ float g_PM[BB * TT * HH];      // prefix-max of u within chunk
__device__ float g_Vt[BB * TT * HH];      // v * e^u
__device__ float g_P[BB * TT * HH];       // prefix-sum of k * e^u
__device__ float g_G[BB * TT * HH];       // intra-chunk numerator (pre e^{-M})
__device__ float g_Gc[BB * NC * HH * HH]; // per-chunk  Vt^T K
__device__ float g_Cst[BB * NC * HH * HH];// C state at each chunk start
__device__ float g_aL[BB * NC * HH];      // chunk-final cumsum(f)
__device__ float g_m0s[BB * NC * HH];     // m at chunk start
__device__ float g_n0s[BB * NC * HH];     // n at chunk start
__device__ float g_rden[BB * TT];         // 1 / denom

static __device__ __forceinline__ unsigned su32(const void* p) {
    return (unsigned)__cvta_generic_to_shared(p);
}

extern __shared__ float dsm[];

// ===========================================================================
// GEMM: Out[m][n] = (sum_k X[m][k]*Wseg[nloc][k] + Bseg[nloc]) * scale[seg]
// ===========================================================================
struct GemmArgs {
    const float* W[6];
    const float* Bi[6];
    float scale[6];
    int sigm[6];
};

__global__ __launch_bounds__(256) void gemm_k(int mode, const float* __restrict__ Xp, GemmArgs a)
{
    const int K = 128;
    const int Ntot = (mode == 0) ? 512 : 768;
    const float* __restrict__ X = (mode == 0) ? Xp : g_h1;
    float* __restrict__ Out = (mode == 0) ? g_Wx : g_proj;

    __shared__ float Xs[64][68];
    __shared__ float Ws[64][68];

    const int bm = blockIdx.y * 64;
    const int bn = blockIdx.x * 64;
    const int seg = bn >> 7;
    const int nl0 = bn & 127;
    const float* __restrict__ W = a.W[seg];
    const int tid = threadIdx.x;

    const int tx = tid & 15, ty = tid >> 4;
    float acc[4][4];
#pragma unroll
    for (int i = 0; i < 4; i++)
#pragma unroll
        for (int j = 0; j < 4; j++) acc[i][j] = 0.f;

    const int c4 = tid & 15;
    const int r0 = tid >> 4;

    for (int k0 = 0; k0 < K; k0 += 64) {
        __syncthreads();
#pragma unroll
        for (int rr = r0; rr < 64; rr += 16) {
            float4 xv = *(const float4*)&X[(size_t)(bm + rr) * K + k0 + c4 * 4];
            Xs[c4 * 4 + 0][rr] = xv.x; Xs[c4 * 4 + 1][rr] = xv.y;
            Xs[c4 * 4 + 2][rr] = xv.z; Xs[c4 * 4 + 3][rr] = xv.w;
            float4 wv = *(const float4*)&W[(size_t)(nl0 + rr) * K + k0 + c4 * 4];
            Ws[c4 * 4 + 0][rr] = wv.x; Ws[c4 * 4 + 1][rr] = wv.y;
            Ws[c4 * 4 + 2][rr] = wv.z; Ws[c4 * 4 + 3][rr] = wv.w;
        }
        __syncthreads();
#pragma unroll 4
        for (int k = 0; k < 64; k++) {
            float4 xm = *(const float4*)&Xs[k][ty * 4];
            float4 wn = *(const float4*)&Ws[k][tx * 4];
            float xa[4] = {xm.x, xm.y, xm.z, xm.w};
            float wa[4] = {wn.x, wn.y, wn.z, wn.w};
#pragma unroll
            for (int i = 0; i < 4; i++)
#pragma unroll
                for (int j = 0; j < 4; j++)
                    acc[i][j] = fmaf(xa[i], wa[j], acc[i][j]);
        }
    }

    const float sc = a.scale[seg];
    const int sg = a.sigm[seg];
    const float* __restrict__ Bp = a.Bi[seg];
#pragma unroll
    for (int i = 0; i < 4; i++) {
        int m = bm + ty * 4 + i;
#pragma unroll
        for (int j = 0; j < 4; j++) {
            int nl = nl0 + tx * 4 + j;
            float v = (acc[i][j] + Bp[nl]) * sc;
            if (sg) v = 1.f / (1.f + __expf(-v));
            Out[(size_t)m * Ntot + bn + tx * 4 + j] = v;
        }
    }
}

// ===========================================================================
// sLSTM scan: cluster of 4 CTAs per batch, 128 threads/CTA.
// thread = (unit_local, gate); gates of a unit sit in 4 adjacent lanes.
// h exchange via DSMEM store + per-CTA mbarrier (count 128), double-buffered.
// ===========================================================================
__global__ void __cluster_dims__(4, 1, 1) __launch_bounds__(128, 1)
slstm_k(const float* __restrict__ sR)
{
    __shared__ float h_s[2][HH];
    __shared__ __align__(8) unsigned long long mbar;

    const int tid = threadIdx.x;
    const unsigned rank = (unsigned)(blockIdx.x & 3);
    const int batch = blockIdx.x >> 2;
    const int gate = tid & 3;
    const int ul = tid >> 2;                    // 0..31
    const int gu = (int)rank * 32 + ul;         // global unit of this lane-group
    const int row = gate * 128 + gu;            // row in fused [i,f,z,o] weight

    // --- recurrent weights into registers ---
    float w[128];
    {
        const float4* wr = (const float4*)(sR + (size_t)row * 128);
#pragma unroll
        for (int k4 = 0; k4 < 32; k4++) {
            float4 v = wr[k4];
            w[4 * k4 + 0] = v.x; w[4 * k4 + 1] = v.y;
            w[4 * k4 + 2] = v.z; w[4 * k4 + 3] = v.w;
        }
    }
    h_s[0][tid] = 0.f;
    h_s[1][tid] = 0.f;
    if (tid == 0) {
        unsigned a = su32(&mbar);
        asm volatile("mbarrier.init.shared.b64 [%0], %1;" :: "r"(a), "r"(128) : "memory");
    }
    __syncthreads();
    asm volatile("barrier.cluster.arrive;\n\tbarrier.cluster.wait;\n" ::: "memory");

    // destination CTA of this lane's h store / arrive
    const unsigned dst = (rank + (unsigned)gate) & 3;
    const unsigned mbar_l = su32(&mbar);
    unsigned mbar_d, h_d0;
    {
        unsigned hl0 = su32(&h_s[0][gu]);
        asm("mapa.shared::cluster.u32 %0, %1, %2;" : "=r"(mbar_d) : "r"(mbar_l), "r"(dst));
        asm("mapa.shared::cluster.u32 %0, %1, %2;" : "=r"(h_d0) : "r"(hl0), "r"(dst));
    }

    float c = 0.f, n = 0.f, m = 0.f;
    const float* __restrict__ wx = g_Wx + (size_t)batch * TT * 512 + row;
    float* __restrict__ h1o = g_h1 + (size_t)batch * TT * HH;

    const int lw = tid & 31;            // lane in warp
    const int gb = lw & ~3;             // lane-group base

    float wx_cur = wx[0];

    for (int t = 0; t < TT; t++) {
        const int buf = t & 1;
        float wx_nxt = (t + 1 < TT) ? wx[(size_t)(t + 1) * 512] : 0.f;

        float a0 = 0.f, a1 = 0.f, a2 = 0.f, a3 = 0.f;
        const float4* h4 = (const float4*)h_s[buf];
#pragma unroll
        for (int k4 = 0; k4 < 32; k4++) {
            float4 hv = h4[k4];
            a0 = fmaf(w[4 * k4 + 0], hv.x, a0);
            a1 = fmaf(w[4 * k4 + 1], hv.y, a1);
            a2 = fmaf(w[4 * k4 + 2], hv.z, a2);
            a3 = fmaf(w[4 * k4 + 3], hv.w, a3);
        }
        float g = ((a0 + a1) + (a2 + a3)) + wx_cur;

        __syncthreads();   // all local lanes done reading h_s[buf]

        float gi = __shfl_sync(0xffffffffu, g, gb + 0, 32);
        float gf = __shfl_sync(0xffffffffu, g, gb + 1, 32);
        float gz = __shfl_sync(0xffffffffu, g, gb + 2, 32);
        float go = __shfl_sync(0xffffffffu, g, gb + 3, 32);

        float mn = fmaxf(gf + m, gi);
        float ii = __expf(gi - mn);
        float ff = __expf(gf + m - mn);
        c = ff * c + ii * tanhf(gz);
        n = ff * n + ii;
        m = mn;
        float hn = (c / n) * (1.f / (1.f + __expf(-go)));

        const int nb = buf ^ 1;
        unsigned haddr = h_d0 + (unsigned)(nb * (HH * 4));
        asm volatile("st.shared::cluster.f32 [%0], %1;" :: "r"(haddr), "f"(hn) : "memory");
        if (gate == 0) h1o[(size_t)t * HH + gu] = hn;

        asm volatile("mbarrier.arrive.release.cluster.shared::cluster.b64 _, [%0];"
                     :: "r"(mbar_d) : "memory");

        {
            unsigned par = (unsigned)(t & 1);
            asm volatile(
                "{\n\t"
                ".reg .pred P;\n\t"
                "WLOOP%=:\n\t"
                "mbarrier.try_wait.parity.acquire.cluster.shared::cta.b64 P, [%0], %1, 0x989680;\n\t"
                "@P bra.uni WDONE%=;\n\t"
                "bra.uni WLOOP%=;\n\t"
                "WDONE%=:\n\t"
                "}"
                :: "r"(mbar_l), "r"(par) : "memory");
        }
        wx_cur = wx_nxt;
    }

    asm volatile("barrier.cluster.arrive;\n\tbarrier.cluster.wait;\n" ::: "memory");
}

// ===========================================================================
// mLSTM chunkwise-parallel pipeline
// ===========================================================================

// ---- prep: per (b,c,j): a=cumsum(f), u=i-a, PM=prefmax(u), Vt=v*e^u, P=cumsum(k*e^u)
//      with one-step-ahead prefetch to break the load-latency chain.
__global__ __launch_bounds__(128) void prep_k()
{
    const int b = blockIdx.x >> 4;
    const int c = blockIdx.x & 15;
    const int j = threadIdx.x;
    const float* __restrict__ base = g_proj + ((size_t)(b * TT + c * LL) * 768) + j;
    float a = 0.f, pm = -1e30f, p = 0.f;
    size_t oidx = (size_t)(b * TT + c * LL) * HH + j;

    float fv = base[512], iv = base[384], vv = base[256], kv = base[128];
    for (int t = 0; t < LL; t++) {
        float fn = 0.f, in_ = 0.f, vn = 0.f, kn = 0.f;
        if (t + 1 < LL) {
            const float* nxt = base + (size_t)(t + 1) * 768;
            fn = nxt[512]; in_ = nxt[384]; vn = nxt[256]; kn = nxt[128];
        }
        a += fv;
        float u = iv - a;
        pm = fmaxf(pm, u);
        float eu = __expf(u);
        g_PM[oidx] = pm;
        g_Vt[oidx] = vv * eu;
        p = fmaf(kv, eu, p);
        g_P[oidx] = p;
        oidx += HH;
        fv = fn; iv = in_; vv = vn; kv = kn;
    }
    g_aL[(b * NC + c) * HH + j] = a;
}

// ---- chunk-boundary scan for m0 and n0 (per (b,j), 16 serial chunks)
__global__ __launch_bounds__(128) void n0m0_k()
{
    const int b = blockIdx.x;
    const int j = threadIdx.x;
    float m0 = 0.f, n0 = 0.f;
    for (int c = 0; c < NC; c++) {
        int ci = (b * NC + c) * HH + j;
        g_m0s[ci] = m0;
        g_n0s[ci] = n0;
        size_t li = (size_t)(b * TT + c * LL + (LL - 1)) * HH + j;
        float pml = g_PM[li];
        float pl  = g_P[li];
        float ML = fmaxf(m0, pml);
        n0 = __expf(m0 - ML) * n0 + __expf(-ML) * pl;
        m0 = g_aL[ci] + ML;
    }
}

// ---- Gc[b][c] = Vt^T K   (H x H per chunk)
__global__ __launch_bounds__(256) void gc_k()
{
    float* Vs = dsm;                // [64][128]
    float* Ks = dsm + 64 * 128;     // [64][132] padded
    const int b = blockIdx.x >> 4, c = blockIdx.x & 15;
    const int tid = threadIdx.x;
    const float* __restrict__ vb = g_Vt + (size_t)(b * TT + c * LL) * HH;
    const float* __restrict__ pb = g_proj + (size_t)(b * TT + c * LL) * 768;
    for (int i = tid; i < 2048; i += 256) {
        int s = i >> 5, j4 = i & 31;
        ((float4*)Vs)[i] = ((const float4*)vb)[i];
        float4 kv = *(const float4*)(pb + (size_t)s * 768 + 128 + j4 * 4);
        *(float4*)(Ks + s * 132 + j4 * 4) = kv;
    }
    __syncthreads();
    const int r0 = (tid >> 4) * 8, j0 = (tid & 15) * 8;
    float acc[8][8];
#pragma unroll
    for (int i = 0; i < 8; i++)
#pragma unroll
        for (int jj = 0; jj < 8; jj++) acc[i][jj] = 0.f;
    for (int s = 0; s < 64; s++) {
        float4 va = *(float4*)(Vs + s * 128 + r0);
        float4 vb4 = *(float4*)(Vs + s * 128 + r0 + 4);
        float4 ka = *(float4*)(Ks + s * 132 + j0);
        float4 kb = *(float4*)(Ks + s * 132 + j0 + 4);
        float vr[8] = {va.x, va.y, va.z, va.w, vb4.x, vb4.y, vb4.z, vb4.w};
        float kj[8] = {ka.x, ka.y, ka.z, ka.w, kb.x, kb.y, kb.z, kb.w};
#pragma unroll
        for (int i = 0; i < 8; i++)
#pragma unroll
            for (int jj = 0; jj < 8; jj++)
                acc[i][jj] = fmaf(vr[i], kj[jj], acc[i][jj]);
    }
    float* gout = g_Gc + (size_t)(b * NC + c) * (HH * HH);
#pragma unroll
    for (int i = 0; i < 8; i++)
#pragma unroll
        for (int jj = 0; jj < 8; jj += 4) {
            float4 v = {acc[i][jj], acc[i][jj + 1], acc[i][jj + 2], acc[i][jj + 3]};
            *(float4*)(gout + (size_t)(r0 + i) * HH + j0 + jj) = v;
        }
}

// ---- S = QK^T (causal-masked), G = S * Vt   per (b,c)
__global__ __launch_bounds__(256) void sg_k()
{
    float* Qs = dsm;                          // [64][128]
    float* KV = dsm + 64 * 128;               // [64][132] K then Vt
    float* Ss = dsm + 64 * 128 + 64 * 132;    // [64][65]
    const int b = blockIdx.x >> 4, c = blockIdx.x & 15;
    const int tid = threadIdx.x;
    const float* __restrict__ pb = g_proj + (size_t)(b * TT + c * LL) * 768;
    const float* __restrict__ vb = g_Vt + (size_t)(b * TT + c * LL) * HH;
    for (int i = tid; i < 2048; i += 256) {
        int s = i >> 5, j4 = i & 31;
        *(float4*)(Qs + s * 128 + j4 * 4) = *(const float4*)(pb + (size_t)s * 768 + j4 * 4);
        *(float4*)(KV + s * 132 + j4 * 4) = *(const float4*)(pb + (size_t)s * 768 + 128 + j4 * 4);
    }
    __syncthreads();
    {
        const int t0 = (tid >> 4) * 4, s0 = (tid & 15) * 4;
        float acc[4][4];
#pragma unroll
        for (int i = 0; i < 4; i++)
#pragma unroll
            for (int s = 0; s < 4; s++) acc[i][s] = 0.f;
        for (int jj = 0; jj < 128; jj += 4) {
            float4 q[4], k[4];
#pragma unroll
            for (int i = 0; i < 4; i++) q[i] = *(float4*)(Qs + (t0 + i) * 128 + jj);
#pragma unroll
            for (int s = 0; s < 4; s++) k[s] = *(float4*)(KV + (s0 + s) * 132 + jj);
#pragma unroll
            for (int i = 0; i < 4; i++)
#pragma unroll
                for (int s = 0; s < 4; s++)
                    acc[i][s] += q[i].x * k[s].x + q[i].y * k[s].y
                               + q[i].z * k[s].z + q[i].w * k[s].w;
        }
#pragma unroll
        for (int i = 0; i < 4; i++)
#pragma unroll
            for (int s = 0; s < 4; s++)
                Ss[(t0 + i) * 65 + s0 + s] = (s0 + s <= t0 + i) ? acc[i][s] : 0.f;
    }
    __syncthreads();
    for (int i = tid; i < 2048; i += 256) {
        int s = i >> 5, j4 = i & 31;
        *(float4*)(KV + s * 132 + j4 * 4) = *(const float4*)(vb + (size_t)s * HH + j4 * 4);
    }
    __syncthreads();
    {
        const int t0 = (tid >> 5) * 8, r0 = (tid & 31) * 4;
        float acc[8][4];
#pragma unroll
        for (int i = 0; i < 8; i++)
#pragma unroll
            for (int jj = 0; jj < 4; jj++) acc[i][jj] = 0.f;
        for (int s = 0; s < 64; s++) {
            float4 v = *(float4*)(KV + s * 132 + r0);
#pragma unroll
            for (int i = 0; i < 8; i++) {
                float sv = Ss[(t0 + i) * 65 + s];
                acc[i][0] = fmaf(sv, v.x, acc[i][0]);
                acc[i][1] = fmaf(sv, v.y, acc[i][1]);
                acc[i][2] = fmaf(sv, v.z, acc[i][2]);
                acc[i][3] = fmaf(sv, v.w, acc[i][3]);
            }
        }
        float* gout = g_G + (size_t)(b * TT + c * LL) * HH;
#pragma unroll
        for (int i = 0; i < 8; i++) {
            float4 o4 = {acc[i][0], acc[i][1], acc[i][2], acc[i][3]};
            *(float4*)(gout + (size_t)(t0 + i) * HH + r0) = o4;
        }
    }
}

// ---- element-parallel C scan over 16 chunks: stores chunk-start C
__global__ __launch_bounds__(256) void cscan_k()
{
    int idx = blockIdx.x * 256 + threadIdx.x;
    int b = idx >> 14;
    int rj = idx & 16383;
    int r = rj >> 7;
    float C = 0.f;
    for (int c = 0; c < NC; c++) {
        size_t so = (size_t)(b * NC + c) * 16384 + rj;
        g_Cst[so] = C;
        float m0 = g_m0s[(b * NC + c) * HH + r];
        float pml = g_PM[(size_t)(b * TT + c * LL + LL - 1) * HH + r];
        float ML = fmaxf(m0, pml);
        C = __expf(m0 - ML) * C + __expf(-ML) * g_Gc[so];
    }
}

// ---- denominators (fully parallel over t): den = q . n_t
__global__ __launch_bounds__(256) void den_k()
{
    int g = blockIdx.x * 8 + (threadIdx.x >> 5);
    int lane = threadIdx.x & 31;
    int b = g >> 10, t = g & 1023;
    int c = t >> 6;
    int j0 = lane * 4;
    const float* q = g_proj + (size_t)(b * TT + t) * 768;
    size_t gi = (size_t)(b * TT + t) * HH;
    int ci = (b * NC + c) * HH;
    float d = 0.f;
#pragma unroll
    for (int s = 0; s < 4; s++) {
        int j = j0 + s;
        float m0 = g_m0s[ci + j];
        float pm = g_PM[gi + j];
        float g1 = __expf(fminf(0.f, m0 - pm));
        float g2 = fminf(__expf(-m0), __expf(-pm));
        float nv = g1 * g_n0s[ci + j] + g2 * g_P[gi + j];
        d = fmaf(q[j], nv, d);
    }
#pragma unroll
    for (int s2 = 16; s2 >= 1; s2 >>= 1)
        d += __shfl_xor_sync(0xffffffffu, d, s2);
    if (lane == 0) g_rden[g] = 1.f / fmaxf(fabsf(d), 1.f);
}

// ---- final: h = o * (e^{m0-M} C0 q + e^{-M} G) * rden
__global__ __launch_bounds__(256) void inter_k(float* __restrict__ out)
{
    __shared__ float qs[16][128];
    const int blk = blockIdx.x;
    const int b = blk >> 6;
    const int c = (blk >> 2) & 15;
    const int tb = blk & 3;
    const int tid = threadIdx.x;
    const int r = tid >> 1, half = tid & 1;
    const int t0 = c * LL + tb * 16;

    const float* pb = g_proj + (size_t)(b * TT + t0) * 768;
    for (int i = tid; i < 512; i += 256) {
        int tt = i >> 5, j4 = i & 31;
        *(float4*)(&qs[tt][j4 * 4]) = *(const float4*)(pb + (size_t)tt * 768 + j4 * 4);
    }
    float Creg[64];
    const float* cb = g_Cst + (size_t)(b * NC + c) * 16384 + (size_t)r * 128 + half * 64;
#pragma unroll
    for (int i = 0; i < 16; i++) {
        float4 v = *(const float4*)(cb + i * 4);
        Creg[4 * i] = v.x; Creg[4 * i + 1] = v.y;
        Creg[4 * i + 2] = v.z; Creg[4 * i + 3] = v.w;
    }
    float m0 = g_m0s[(b * NC + c) * HH + r];
    float em0a = __expf(-m0);
    __syncthreads();

    for (int tt = 0; tt < 16; tt++) {
        float acc = 0.f;
        const float* qrow = &qs[tt][half * 64];
#pragma unroll
        for (int i = 0; i < 16; i++) {
            float4 qv = *(const float4*)(qrow + i * 4);
            acc = fmaf(Creg[4 * i], qv.x, acc);
            acc = fmaf(Creg[4 * i + 1], qv.y, acc);
            acc = fmaf(Creg[4 * i + 2], qv.z, acc);
            acc = fmaf(Creg[4 * i + 3], qv.w, acc);
        }
        acc += __shfl_xor_sync(0xffffffffu, acc, 1);
        if (half == 0) {
            int t = t0 + tt;
            size_t gi = (size_t)(b * TT + t) * HH + r;
            float pm = g_PM[gi];
            float g1 = __expf(fminf(0.f, m0 - pm));
            float g2 = fminf(em0a, __expf(-pm));
            float htl = g1 * acc + g2 * g_G[gi];
            float o = g_proj[(size_t)(b * TT + t) * 768 + 640 + r];
            out[gi] = o * htl * g_rden[b * TT + t];
        }
    }
}

// ===========================================================================
extern "C" void kernel_launch(void* const* d_in, const int* in_sizes, int n_in,
                              void* d_out, int out_size)
{
    const float* x  = (const float*)d_in[0];
    const float* sW = (const float*)d_in[1];
    const float* sR = (const float*)d_in[2];
    const float* sb = (const float*)d_in[3];
    const float* Wq = (const float*)d_in[4];
    const float* Wk = (const float*)d_in[5];
    const float* Wv = (const float*)d_in[6];
    const float* Wi = (const float*)d_in[7];
    const float* Wf = (const float*)d_in[8];
    const float* Wo = (const float*)d_in[9];
    const float* bq = (const float*)d_in[10];
    const float* bk = (const float*)d_in[11];
    const float* bv = (const float*)d_in[12];
    const float* bi = (const float*)d_in[13];
    const float* bf = (const float*)d_in[14];
    const float* bo = (const float*)d_in[15];

    const int GC_SMEM = (64 * 128 + 64 * 132) * 4;
    const int SG_SMEM = (64 * 128 + 64 * 132 + 64 * 65) * 4;
    cudaFuncSetAttribute(gc_k, cudaFuncAttributeMaxDynamicSharedMemorySize, GC_SMEM);
    cudaFuncSetAttribute(sg_k, cudaFuncAttributeMaxDynamicSharedMemorySize, SG_SMEM);

    // GEMM1: Wx = x @ sW^T + sb
    GemmArgs a1;
    for (int s = 0; s < 6; s++) {
        int ss = (s < 4) ? s : 3;
        a1.W[s] = sW + (size_t)ss * 128 * 128;
        a1.Bi[s] = sb + (size_t)ss * 128;
        a1.scale[s] = 1.f;
        a1.sigm[s] = 0;
    }
    gemm_k<<<dim3(8, 128), 256>>>(0, x, a1);

    // sLSTM scan (cluster 4 per batch)
    slstm_k<<<32, 128>>>(sR);

    // GEMM2: proj = h1 @ [Wq Wk Wv Wi Wf Wo]^T + biases (k scaled, o sigmoided)
    GemmArgs a2;
    const float* Ws2[6] = {Wq, Wk, Wv, Wi, Wf, Wo};
    const float* Bs2[6] = {bq, bk, bv, bi, bf, bo};
    const float inv_sqrt_h = 0.08838834764831845f;
    for (int s = 0; s < 6; s++) {
        a2.W[s] = Ws2[s];
        a2.Bi[s] = Bs2[s];
        a2.scale[s] = (s == 1) ? inv_sqrt_h : 1.f;
        a2.sigm[s] = (s == 5) ? 1 : 0;
    }
    gemm_k<<<dim3(12, 128), 256>>>(1, nullptr, a2);

    // mLSTM chunkwise pipeline
    prep_k<<<BB * NC, 128>>>();
    gc_k<<<BB * NC, 256, GC_SMEM>>>();
    sg_k<<<BB * NC, 256, SG_SMEM>>>();
    n0m0_k<<<BB, 128>>>();
    cscan_k<<<(BB * HH * HH) / 256, 256>>>();
    den_k<<<(BB * TT) / 8, 256>>>();
    inter_k<<<BB * NC * 4, 256>>>((float*)d_out);
}

// round 5
// speedup vs baseline: 1.4556x; 1.0395x over previous
#include <cuda_runtime.h>
#include <cuda_bf16.h>
#include <cstdint>

#define BB 8
#define TT 1024
#define HH 128
#define LL 64      // mLSTM chunk length
#define NC 16      // TT / LL

// ---------------- static device scratch (no allocation APIs) ---------------
__device__ float g_Wx[BB * TT * 512];     // sLSTM input projections (+sb)
__device__ float g_h1[BB * TT * HH];      // sLSTM output sequence
__device__ float g_proj[BB * TT * 768];   // mLSTM projections [q k v i f o]
__device__ float g_PM[BB * TT * HH];      // prefix-max of u within chunk
__device__ float g_Vt[BB * TT * HH];      // v * e^u
__device__ float g_P[BB * TT * HH];       // prefix-sum of k * e^u
__device__ float g_G[BB * TT * HH];       // intra-chunk numerator (pre e^{-M})
__device__ float g_Gc[BB * NC * HH * HH]; // per-chunk  Vt^T K
__device__ float g_Cst[BB * NC * HH * HH];// C state at each chunk start
__device__ float g_aL[BB * NC * HH];      // chunk-final cumsum(f)
__device__ float g_m0s[BB * NC * HH];     // m at chunk start
__device__ float g_n0s[BB * NC * HH];     // n at chunk start
__device__ float g_rden[BB * TT];         // 1 / denom

static __device__ __forceinline__ unsigned su32(const void* p) {
    return (unsigned)__cvta_generic_to_shared(p);
}

// ---- f32x2 packed helpers (sm_100+) ----
static __device__ __forceinline__ unsigned long long pack2(float a, float b) {
    unsigned long long r;
    asm("mov.b64 %0, {%1, %2};" : "=l"(r) : "f"(a), "f"(b));
    return r;
}
static __device__ __forceinline__ void fma2(unsigned long long& d,
                                            unsigned long long a,
                                            unsigned long long b) {
    asm("fma.rn.f32x2 %0, %1, %2, %0;" : "+l"(d) : "l"(a), "l"(b));
}
static __device__ __forceinline__ float2 unpack2(unsigned long long v) {
    float2 f;
    asm("mov.b64 {%0, %1}, %2;" : "=f"(f.x), "=f"(f.y) : "l"(v));
    return f;
}
static __device__ __forceinline__ float tanh_fast(float x) {
    float r;
    asm("tanh.approx.f32 %0, %1;" : "=f"(r) : "f"(x));
    return r;
}

extern __shared__ float dsm[];

// ===========================================================================
// GEMM: Out[m][n] = (sum_k X[m][k]*Wseg[nloc][k] + Bseg[nloc]) * scale[seg]
// ===========================================================================
struct GemmArgs {
    const float* W[6];
    const float* Bi[6];
    float scale[6];
    int sigm[6];
};

__global__ __launch_bounds__(256) void gemm_k(int mode, const float* __restrict__ Xp, GemmArgs a)
{
    const int K = 128;
    const int Ntot = (mode == 0) ? 512 : 768;
    const float* __restrict__ X = (mode == 0) ? Xp : g_h1;
    float* __restrict__ Out = (mode == 0) ? g_Wx : g_proj;

    __shared__ float Xs[64][68];
    __shared__ float Ws[64][68];

    const int bm = blockIdx.y * 64;
    const int bn = blockIdx.x * 64;
    const int seg = bn >> 7;
    const int nl0 = bn & 127;
    const float* __restrict__ W = a.W[seg];
    const int tid = threadIdx.x;

    const int tx = tid & 15, ty = tid >> 4;
    float acc[4][4];
#pragma unroll
    for (int i = 0; i < 4; i++)
#pragma unroll
        for (int j = 0; j < 4; j++) acc[i][j] = 0.f;

    const int c4 = tid & 15;
    const int r0 = tid >> 4;

    for (int k0 = 0; k0 < K; k0 += 64) {
        __syncthreads();
#pragma unroll
        for (int rr = r0; rr < 64; rr += 16) {
            float4 xv = *(const float4*)&X[(size_t)(bm + rr) * K + k0 + c4 * 4];
            Xs[c4 * 4 + 0][rr] = xv.x; Xs[c4 * 4 + 1][rr] = xv.y;
            Xs[c4 * 4 + 2][rr] = xv.z; Xs[c4 * 4 + 3][rr] = xv.w;
            float4 wv = *(const float4*)&W[(size_t)(nl0 + rr) * K + k0 + c4 * 4];
            Ws[c4 * 4 + 0][rr] = wv.x; Ws[c4 * 4 + 1][rr] = wv.y;
            Ws[c4 * 4 + 2][rr] = wv.z; Ws[c4 * 4 + 3][rr] = wv.w;
        }
        __syncthreads();
#pragma unroll 4
        for (int k = 0; k < 64; k++) {
            float4 xm = *(const float4*)&Xs[k][ty * 4];
            float4 wn = *(const float4*)&Ws[k][tx * 4];
            float xa[4] = {xm.x, xm.y, xm.z, xm.w};
            float wa[4] = {wn.x, wn.y, wn.z, wn.w};
#pragma unroll
            for (int i = 0; i < 4; i++)
#pragma unroll
                for (int j = 0; j < 4; j++)
                    acc[i][j] = fmaf(xa[i], wa[j], acc[i][j]);
        }
    }

    const float sc = a.scale[seg];
    const int sg = a.sigm[seg];
    const float* __restrict__ Bp = a.Bi[seg];
#pragma unroll
    for (int i = 0; i < 4; i++) {
        int m = bm + ty * 4 + i;
#pragma unroll
        for (int j = 0; j < 4; j++) {
            int nl = nl0 + tx * 4 + j;
            float v = (acc[i][j] + Bp[nl]) * sc;
            if (sg) v = 1.f / (1.f + __expf(-v));
            Out[(size_t)m * Ntot + bn + tx * 4 + j] = v;
        }
    }
}

// ===========================================================================
// sLSTM scan: cluster of 4 CTAs per batch, 128 threads/CTA.
// thread = (unit_local, gate); gates of a unit sit in 4 adjacent lanes.
// matvec in packed f32x2; h exchange via DSMEM + per-CTA mbarrier.
// ===========================================================================
__global__ void __cluster_dims__(4, 1, 1) __launch_bounds__(128, 1)
slstm_k(const float* __restrict__ sR)
{
    __shared__ __align__(16) float h_s[2][HH];
    __shared__ __align__(8) unsigned long long mbar;

    const int tid = threadIdx.x;
    const unsigned rank = (unsigned)(blockIdx.x & 3);
    const int batch = blockIdx.x >> 2;
    const int gate = tid & 3;
    const int ul = tid >> 2;                    // 0..31
    const int gu = (int)rank * 32 + ul;         // global unit of this lane-group
    const int row = gate * 128 + gu;            // row in fused [i,f,z,o] weight

    // --- recurrent weights packed into 64 f32x2 registers ---
    unsigned long long w2[64];
    {
        const float4* wr = (const float4*)(sR + (size_t)row * 128);
#pragma unroll
        for (int k4 = 0; k4 < 32; k4++) {
            float4 v = wr[k4];
            w2[2 * k4 + 0] = pack2(v.x, v.y);
            w2[2 * k4 + 1] = pack2(v.z, v.w);
        }
    }
    h_s[0][tid] = 0.f;
    h_s[1][tid] = 0.f;
    if (tid == 0) {
        unsigned a = su32(&mbar);
        asm volatile("mbarrier.init.shared.b64 [%0], %1;" :: "r"(a), "r"(128) : "memory");
    }
    __syncthreads();
    asm volatile("barrier.cluster.arrive;\n\tbarrier.cluster.wait;\n" ::: "memory");

    const unsigned dst = (rank + (unsigned)gate) & 3;
    const unsigned mbar_l = su32(&mbar);
    unsigned mbar_d, h_d0;
    {
        unsigned hl0 = su32(&h_s[0][gu]);
        asm("mapa.shared::cluster.u32 %0, %1, %2;" : "=r"(mbar_d) : "r"(mbar_l), "r"(dst));
        asm("mapa.shared::cluster.u32 %0, %1, %2;" : "=r"(h_d0) : "r"(hl0), "r"(dst));
    }

    float c = 0.f, n = 0.f, m = 0.f;
    const float* __restrict__ wx = g_Wx + (size_t)batch * TT * 512 + row;
    float* __restrict__ h1o = g_h1 + (size_t)batch * TT * HH;

    const int lw = tid & 31;
    const int gb = lw & ~3;

    float wx_cur = wx[0];

    for (int t = 0; t < TT; t++) {
        const int buf = t & 1;
        float wx_nxt = (t + 1 < TT) ? wx[(size_t)(t + 1) * 512] : 0.f;

        // packed matvec: 64 FFMA2 over 4 independent chains
        unsigned long long a0 = 0ull, a1 = 0ull, a2 = 0ull, a3 = 0ull;
        const ulonglong2* h2 = (const ulonglong2*)h_s[buf];
#pragma unroll
        for (int k = 0; k < 16; k++) {
            ulonglong2 hA = h2[2 * k];       // h[8k .. 8k+3]
            ulonglong2 hB = h2[2 * k + 1];   // h[8k+4 .. 8k+7]
            fma2(a0, w2[4 * k + 0], hA.x);
            fma2(a1, w2[4 * k + 1], hA.y);
            fma2(a2, w2[4 * k + 2], hB.x);
            fma2(a3, w2[4 * k + 3], hB.y);
        }
        float2 f0 = unpack2(a0), f1 = unpack2(a1), f2 = unpack2(a2), f3 = unpack2(a3);
        float g = (((f0.x + f0.y) + (f1.x + f1.y)) + ((f2.x + f2.y) + (f3.x + f3.y))) + wx_cur;

        __syncthreads();   // all local lanes done reading h_s[buf]

        float gi = __shfl_sync(0xffffffffu, g, gb + 0, 32);
        float gf = __shfl_sync(0xffffffffu, g, gb + 1, 32);
        float gz = __shfl_sync(0xffffffffu, g, gb + 2, 32);
        float go = __shfl_sync(0xffffffffu, g, gb + 3, 32);

        float mn = fmaxf(gf + m, gi);
        float ii = __expf(gi - mn);
        float ff = __expf(gf + m - mn);
        c = ff * c + ii * tanh_fast(gz);
        n = ff * n + ii;
        m = mn;
        float sg = __fdividef(1.f, 1.f + __expf(-go));
        float hn = __fdividef(c, n) * sg;

        const int nb = buf ^ 1;
        unsigned haddr = h_d0 + (unsigned)(nb * (HH * 4));
        asm volatile("st.shared::cluster.f32 [%0], %1;" :: "r"(haddr), "f"(hn) : "memory");
        if (gate == 0) h1o[(size_t)t * HH + gu] = hn;

        asm volatile("mbarrier.arrive.release.cluster.shared::cluster.b64 _, [%0];"
                     :: "r"(mbar_d) : "memory");

        {
            unsigned par = (unsigned)(t & 1);
            asm volatile(
                "{\n\t"
                ".reg .pred P;\n\t"
                "WLOOP%=:\n\t"
                "mbarrier.try_wait.parity.acquire.cluster.shared::cta.b64 P, [%0], %1, 0x989680;\n\t"
                "@P bra.uni WDONE%=;\n\t"
                "bra.uni WLOOP%=;\n\t"
                "WDONE%=:\n\t"
                "}"
                :: "r"(mbar_l), "r"(par) : "memory");
        }
        wx_cur = wx_nxt;
    }

    asm volatile("barrier.cluster.arrive;\n\tbarrier.cluster.wait;\n" ::: "memory");
}

// ===========================================================================
// mLSTM chunkwise-parallel pipeline
// ===========================================================================

// ---- prep: per (b,c,j): a=cumsum(f), u=i-a, PM=prefmax(u), Vt=v*e^u, P=cumsum(k*e^u)
//      4-step grouped loads, double-buffered -> MLP 16
__global__ __launch_bounds__(128) void prep_k()
{
    const int b = blockIdx.x >> 4;
    const int c = blockIdx.x & 15;
    const int j = threadIdx.x;
    const float* __restrict__ base = g_proj + ((size_t)(b * TT + c * LL) * 768) + j;
    float a = 0.f, pm = -1e30f, p = 0.f;
    size_t oidx = (size_t)(b * TT + c * LL) * HH + j;

    float fb[2][4], ib[2][4], vb[2][4], kb[2][4];
#pragma unroll
    for (int s = 0; s < 4; s++) {
        const float* row = base + (size_t)s * 768;
        fb[0][s] = row[512]; ib[0][s] = row[384];
        vb[0][s] = row[256]; kb[0][s] = row[128];
    }
    for (int gidx = 0; gidx < 16; gidx++) {
        const int cb = gidx & 1;
        if (gidx + 1 < 16) {
            const float* gbase = base + (size_t)(gidx + 1) * 4 * 768;
#pragma unroll
            for (int s = 0; s < 4; s++) {
                const float* row = gbase + (size_t)s * 768;
                fb[cb ^ 1][s] = row[512]; ib[cb ^ 1][s] = row[384];
                vb[cb ^ 1][s] = row[256]; kb[cb ^ 1][s] = row[128];
            }
        }
#pragma unroll
        for (int s = 0; s < 4; s++) {
            a += fb[cb][s];
            float u = ib[cb][s] - a;
            pm = fmaxf(pm, u);
            float eu = __expf(u);
            g_PM[oidx] = pm;
            g_Vt[oidx] = vb[cb][s] * eu;
            p = fmaf(kb[cb][s], eu, p);
            g_P[oidx] = p;
            oidx += HH;
        }
    }
    g_aL[(b * NC + c) * HH + j] = a;
}

// ---- chunk-boundary scan for m0 and n0 (per (b,j), 16 serial chunks)
__global__ __launch_bounds__(128) void n0m0_k()
{
    const int b = blockIdx.x;
    const int j = threadIdx.x;
    float m0 = 0.f, n0 = 0.f;
    for (int c = 0; c < NC; c++) {
        int ci = (b * NC + c) * HH + j;
        g_m0s[ci] = m0;
        g_n0s[ci] = n0;
        size_t li = (size_t)(b * TT + c * LL + (LL - 1)) * HH + j;
        float pml = g_PM[li];
        float pl  = g_P[li];
        float ML = fmaxf(m0, pml);
        n0 = __expf(m0 - ML) * n0 + __expf(-ML) * pl;
        m0 = g_aL[ci] + ML;
    }
}

// ---- Gc[b][c] = Vt^T K   (H x H per chunk)
__global__ __launch_bounds__(256) void gc_k()
{
    float* Vs = dsm;                // [64][128]
    float* Ks = dsm + 64 * 128;     // [64][132] padded
    const int b = blockIdx.x >> 4, c = blockIdx.x & 15;
    const int tid = threadIdx.x;
    const float* __restrict__ vb = g_Vt + (size_t)(b * TT + c * LL) * HH;
    const float* __restrict__ pb = g_proj + (size_t)(b * TT + c * LL) * 768;
    for (int i = tid; i < 2048; i += 256) {
        int s = i >> 5, j4 = i & 31;
        ((float4*)Vs)[i] = ((const float4*)vb)[i];
        float4 kv = *(const float4*)(pb + (size_t)s * 768 + 128 + j4 * 4);
        *(float4*)(Ks + s * 132 + j4 * 4) = kv;
    }
    __syncthreads();
    const int r0 = (tid >> 4) * 8, j0 = (tid & 15) * 8;
    float acc[8][8];
#pragma unroll
    for (int i = 0; i < 8; i++)
#pragma unroll
        for (int jj = 0; jj < 8; jj++) acc[i][jj] = 0.f;
    for (int s = 0; s < 64; s++) {
        float4 va = *(float4*)(Vs + s * 128 + r0);
        float4 vb4 = *(float4*)(Vs + s * 128 + r0 + 4);
        float4 ka = *(float4*)(Ks + s * 132 + j0);
        float4 kb = *(float4*)(Ks + s * 132 + j0 + 4);
        float vr[8] = {va.x, va.y, va.z, va.w, vb4.x, vb4.y, vb4.z, vb4.w};
        float kj[8] = {ka.x, ka.y, ka.z, ka.w, kb.x, kb.y, kb.z, kb.w};
#pragma unroll
        for (int i = 0; i < 8; i++)
#pragma unroll
            for (int jj = 0; jj < 8; jj++)
                acc[i][jj] = fmaf(vr[i], kj[jj], acc[i][jj]);
    }
    float* gout = g_Gc + (size_t)(b * NC + c) * (HH * HH);
#pragma unroll
    for (int i = 0; i < 8; i++)
#pragma unroll
        for (int jj = 0; jj < 8; jj += 4) {
            float4 v = {acc[i][jj], acc[i][jj + 1], acc[i][jj + 2], acc[i][jj + 3]};
            *(float4*)(gout + (size_t)(r0 + i) * HH + j0 + jj) = v;
        }
}

// ---- S = QK^T (causal-masked), G = S * Vt   per (b,c)
__global__ __launch_bounds__(256) void sg_k()
{
    float* Qs = dsm;                          // [64][128]
    float* KV = dsm + 64 * 128;               // [64][132] K then Vt
    float* Ss = dsm + 64 * 128 + 64 * 132;    // [64][65]
    const int b = blockIdx.x >> 4, c = blockIdx.x & 15;
    const int tid = threadIdx.x;
    const float* __restrict__ pb = g_proj + (size_t)(b * TT + c * LL) * 768;
    const float* __restrict__ vb = g_Vt + (size_t)(b * TT + c * LL) * HH;
    for (int i = tid; i < 2048; i += 256) {
        int s = i >> 5, j4 = i & 31;
        *(float4*)(Qs + s * 128 + j4 * 4) = *(const float4*)(pb + (size_t)s * 768 + j4 * 4);
        *(float4*)(KV + s * 132 + j4 * 4) = *(const float4*)(pb + (size_t)s * 768 + 128 + j4 * 4);
    }
    __syncthreads();
    {
        const int t0 = (tid >> 4) * 4, s0 = (tid & 15) * 4;
        float acc[4][4];
#pragma unroll
        for (int i = 0; i < 4; i++)
#pragma unroll
            for (int s = 0; s < 4; s++) acc[i][s] = 0.f;
        for (int jj = 0; jj < 128; jj += 4) {
            float4 q[4], k[4];
#pragma unroll
            for (int i = 0; i < 4; i++) q[i] = *(float4*)(Qs + (t0 + i) * 128 + jj);
#pragma unroll
            for (int s = 0; s < 4; s++) k[s] = *(float4*)(KV + (s0 + s) * 132 + jj);
#pragma unroll
            for (int i = 0; i < 4; i++)
#pragma unroll
                for (int s = 0; s < 4; s++)
                    acc[i][s] += q[i].x * k[s].x + q[i].y * k[s].y
                               + q[i].z * k[s].z + q[i].w * k[s].w;
        }
#pragma unroll
        for (int i = 0; i < 4; i++)
#pragma unroll
            for (int s = 0; s < 4; s++)
                Ss[(t0 + i) * 65 + s0 + s] = (s0 + s <= t0 + i) ? acc[i][s] : 0.f;
    }
    __syncthreads();
    for (int i = tid; i < 2048; i += 256) {
        int s = i >> 5, j4 = i & 31;
        *(float4*)(KV + s * 132 + j4 * 4) = *(const float4*)(vb + (size_t)s * HH + j4 * 4);
    }
    __syncthreads();
    {
        const int t0 = (tid >> 5) * 8, r0 = (tid & 31) * 4;
        float acc[8][4];
#pragma unroll
        for (int i = 0; i < 8; i++)
#pragma unroll
            for (int jj = 0; jj < 4; jj++) acc[i][jj] = 0.f;
        for (int s = 0; s < 64; s++) {
            float4 v = *(float4*)(KV + s * 132 + r0);
#pragma unroll
            for (int i = 0; i < 8; i++) {
                float sv = Ss[(t0 + i) * 65 + s];
                acc[i][0] = fmaf(sv, v.x, acc[i][0]);
                acc[i][1] = fmaf(sv, v.y, acc[i][1]);
                acc[i][2] = fmaf(sv, v.z, acc[i][2]);
                acc[i][3] = fmaf(sv, v.w, acc[i][3]);
            }
        }
        float* gout = g_G + (size_t)(b * TT + c * LL) * HH;
#pragma unroll
        for (int i = 0; i < 8; i++) {
            float4 o4 = {acc[i][0], acc[i][1], acc[i][2], acc[i][3]};
            *(float4*)(gout + (size_t)(t0 + i) * HH + r0) = o4;
        }
    }
}

// ---- element-parallel C scan over 16 chunks: stores chunk-start C
__global__ __launch_bounds__(256) void cscan_k()
{
    int idx = blockIdx.x * 256 + threadIdx.x;
    int b = idx >> 14;
    int rj = idx & 16383;
    int r = rj >> 7;
    float C = 0.f;
    for (int c = 0; c < NC; c++) {
        size_t so = (size_t)(b * NC + c) * 16384 + rj;
        g_Cst[so] = C;
        float m0 = g_m0s[(b * NC + c) * HH + r];
        float pml = g_PM[(size_t)(b * TT + c * LL + LL - 1) * HH + r];
        float ML = fmaxf(m0, pml);
        C = __expf(m0 - ML) * C + __expf(-ML) * g_Gc[so];
    }
}

// ---- denominators (fully parallel over t): den = q . n_t
__global__ __launch_bounds__(256) void den_k()
{
    int g = blockIdx.x * 8 + (threadIdx.x >> 5);
    int lane = threadIdx.x & 31;
    int b = g >> 10, t = g & 1023;
    int c = t >> 6;
    int j0 = lane * 4;
    const float* q = g_proj + (size_t)(b * TT + t) * 768;
    size_t gi = (size_t)(b * TT + t) * HH;
    int ci = (b * NC + c) * HH;
    float d = 0.f;
#pragma unroll
    for (int s = 0; s < 4; s++) {
        int j = j0 + s;
        float m0 = g_m0s[ci + j];
        float pm = g_PM[gi + j];
        float g1 = __expf(fminf(0.f, m0 - pm));
        float g2 = fminf(__expf(-m0), __expf(-pm));
        float nv = g1 * g_n0s[ci + j] + g2 * g_P[gi + j];
        d = fmaf(q[j], nv, d);
    }
#pragma unroll
    for (int s2 = 16; s2 >= 1; s2 >>= 1)
        d += __shfl_xor_sync(0xffffffffu, d, s2);
    if (lane == 0) g_rden[g] = 1.f / fmaxf(fabsf(d), 1.f);
}

// ---- final: h = o * (e^{m0-M} C0 q + e^{-M} G) * rden
__global__ __launch_bounds__(256) void inter_k(float* __restrict__ out)
{
    __shared__ float qs[16][128];
    const int blk = blockIdx.x;
    const int b = blk >> 6;
    const int c = (blk >> 2) & 15;
    const int tb = blk & 3;
    const int tid = threadIdx.x;
    const int r = tid >> 1, half = tid & 1;
    const int t0 = c * LL + tb * 16;

    const float* pb = g_proj + (size_t)(b * TT + t0) * 768;
    for (int i = tid; i < 512; i += 256) {
        int tt = i >> 5, j4 = i & 31;
        *(float4*)(&qs[tt][j4 * 4]) = *(const float4*)(pb + (size_t)tt * 768 + j4 * 4);
    }
    float Creg[64];
    const float* cb = g_Cst + (size_t)(b * NC + c) * 16384 + (size_t)r * 128 + half * 64;
#pragma unroll
    for (int i = 0; i < 16; i++) {
        float4 v = *(const float4*)(cb + i * 4);
        Creg[4 * i] = v.x; Creg[4 * i + 1] = v.y;
        Creg[4 * i + 2] = v.z; Creg[4 * i + 3] = v.w;
    }
    float m0 = g_m0s[(b * NC + c) * HH + r];
    float em0a = __expf(-m0);
    __syncthreads();

    for (int tt = 0; tt < 16; tt++) {
        float acc = 0.f;
        const float* qrow = &qs[tt][half * 64];
#pragma unroll
        for (int i = 0; i < 16; i++) {
            float4 qv = *(const float4*)(qrow + i * 4);
            acc = fmaf(Creg[4 * i], qv.x, acc);
            acc = fmaf(Creg[4 * i + 1], qv.y, acc);
            acc = fmaf(Creg[4 * i + 2], qv.z, acc);
            acc = fmaf(Creg[4 * i + 3], qv.w, acc);
        }
        acc += __shfl_xor_sync(0xffffffffu, acc, 1);
        if (half == 0) {
            int t = t0 + tt;
            size_t gi = (size_t)(b * TT + t) * HH + r;
            float pm = g_PM[gi];
            float g1 = __expf(fminf(0.f, m0 - pm));
            float g2 = fminf(em0a, __expf(-pm));
            float htl = g1 * acc + g2 * g_G[gi];
            float o = g_proj[(size_t)(b * TT + t) * 768 + 640 + r];
            out[gi] = o * htl * g_rden[b * TT + t];
        }
    }
}

// ===========================================================================
extern "C" void kernel_launch(void* const* d_in, const int* in_sizes, int n_in,
                              void* d_out, int out_size)
{
    const float* x  = (const float*)d_in[0];
    const float* sW = (const float*)d_in[1];
    const float* sR = (const float*)d_in[2];
    const float* sb = (const float*)d_in[3];
    const float* Wq = (const float*)d_in[4];
    const float* Wk = (const float*)d_in[5];
    const float* Wv = (const float*)d_in[6];
    const float* Wi = (const float*)d_in[7];
    const float* Wf = (const float*)d_in[8];
    const float* Wo = (const float*)d_in[9];
    const float* bq = (const float*)d_in[10];
    const float* bk = (const float*)d_in[11];
    const float* bv = (const float*)d_in[12];
    const float* bi = (const float*)d_in[13];
    const float* bf = (const float*)d_in[14];
    const float* bo = (const float*)d_in[15];

    const int GC_SMEM = (64 * 128 + 64 * 132) * 4;
    const int SG_SMEM = (64 * 128 + 64 * 132 + 64 * 65) * 4;
    cudaFuncSetAttribute(gc_k, cudaFuncAttributeMaxDynamicSharedMemorySize, GC_SMEM);
    cudaFuncSetAttribute(sg_k, cudaFuncAttributeMaxDynamicSharedMemorySize, SG_SMEM);

    // GEMM1: Wx = x @ sW^T + sb
    GemmArgs a1;
    for (int s = 0; s < 6; s++) {
        int ss = (s < 4) ? s : 3;
        a1.W[s] = sW + (size_t)ss * 128 * 128;
        a1.Bi[s] = sb + (size_t)ss * 128;
        a1.scale[s] = 1.f;
        a1.sigm[s] = 0;
    }
    gemm_k<<<dim3(8, 128), 256>>>(0, x, a1);

    // sLSTM scan (cluster 4 per batch)
    slstm_k<<<32, 128>>>(sR);

    // GEMM2: proj = h1 @ [Wq Wk Wv Wi Wf Wo]^T + biases (k scaled, o sigmoided)
    GemmArgs a2;
    const float* Ws2[6] = {Wq, Wk, Wv, Wi, Wf, Wo};
    const float* Bs2[6] = {bq, bk, bv, bi, bf, bo};
    const float inv_sqrt_h = 0.08838834764831845f;
    for (int s = 0; s < 6; s++) {
        a2.W[s] = Ws2[s];
        a2.Bi[s] = Bs2[s];
        a2.scale[s] = (s == 1) ? inv_sqrt_h : 1.f;
        a2.sigm[s] = (s == 5) ? 1 : 0;
    }
    gemm_k<<<dim3(12, 128), 256>>>(1, nullptr, a2);

    // mLSTM chunkwise pipeline
    prep_k<<<BB * NC, 128>>>();
    gc_k<<<BB * NC, 256, GC_SMEM>>>();
    sg_k<<<BB * NC, 256, SG_SMEM>>>();
    n0m0_k<<<BB, 128>>>();
    cscan_k<<<(BB * HH * HH) / 256, 256>>>();
    den_k<<<(BB * TT) / 8, 256>>>();
    inter_k<<<BB * NC * 4, 256>>>((float*)d_out);
}